// round 2
// baseline (speedup 1.0000x reference)
#include <cuda_runtime.h>
#include <cstdint>

#define TOKENS 256
#define NOUT 4096
#define NIN 4096
#define NSPARSE 8388608

// ---------------- GEMM tiling (Ampere-style mma.sync, sm_100 non-'a' safe) ----------------
#define BM 128
#define BN 64
#define BK 32
#define STAGES 4
#define NS (NIN / BK)                 // 128 K-stages

#define A_BYTES (BM * BK * 4)         // 16 KB
#define B_BYTES (BN * BK * 4)         // 8 KB
#define STAGE_BYTES (A_BYTES + B_BYTES)
#define SMEM_TOTAL (STAGES * STAGE_BYTES)   // 96 KB

// ---------------- persistent device scratch (zero-init at module load) ----------------
__device__ float g_W[NOUT * NIN];     // 64 MB dense weight; untouched entries stay 0 forever
__device__ float g_xr[TOKENS * NIN];  // 4 MB tf32-rounded activations

// ---------------- helpers ----------------
__device__ __forceinline__ float tf32r(float a) {
    uint32_t u;
    asm("cvt.rna.tf32.f32 %0, %1;" : "=r"(u) : "f"(a));
    return __uint_as_float(u);
}

__device__ __forceinline__ uint32_t s2u(const void* p) {
    uint32_t a;
    asm("{ .reg .u64 t; cvta.to.shared.u64 t, %1; cvt.u32.u64 %0, t; }" : "=r"(a) : "l"(p));
    return a;
}

__device__ __forceinline__ void cpasync16(uint32_t saddr, const void* g) {
    asm volatile("cp.async.cg.shared.global [%0], [%1], 16;" :: "r"(saddr), "l"(g) : "memory");
}
#define CP_COMMIT() asm volatile("cp.async.commit_group;" ::: "memory")
#define CP_WAIT()   asm volatile("cp.async.wait_group %0;" :: "n"(STAGES - 2) : "memory")

__device__ __forceinline__ void ldsm4(uint32_t& r0, uint32_t& r1, uint32_t& r2, uint32_t& r3,
                                      uint32_t addr) {
    asm volatile("ldmatrix.sync.aligned.m8n8.x4.shared.b16 {%0,%1,%2,%3}, [%4];"
                 : "=r"(r0), "=r"(r1), "=r"(r2), "=r"(r3) : "r"(addr));
}

__device__ __forceinline__ void mma8(float* d, const uint32_t* a, uint32_t b0, uint32_t b1) {
    asm volatile(
        "mma.sync.aligned.m16n8k8.row.col.f32.tf32.tf32.f32 "
        "{%0,%1,%2,%3}, {%4,%5,%6,%7}, {%8,%9}, {%0,%1,%2,%3};"
        : "+f"(d[0]), "+f"(d[1]), "+f"(d[2]), "+f"(d[3])
        : "r"(a[0]), "r"(a[1]), "r"(a[2]), "r"(a[3]), "r"(b0), "r"(b1));
}

// ---------------- prep kernels ----------------
__global__ void round_x_kernel(const float4* __restrict__ x, int nq) {
    int i = blockIdx.x * blockDim.x + threadIdx.x;
    if (i < nq) {
        float4 v = x[i];
        v.x = tf32r(v.x); v.y = tf32r(v.y); v.z = tf32r(v.z); v.w = tf32r(v.w);
        reinterpret_cast<float4*>(g_xr)[i] = v;
    }
}

__global__ void scatter_kernel(const float4* __restrict__ vals, const int4* __restrict__ idx,
                               int nq) {
    int i = blockIdx.x * blockDim.x + threadIdx.x;
    if (i < nq) {
        float4 v = vals[i];
        int4 id = idx[i];
        // tf32-RN pre-rounding kills the MMA's internal truncation bias
        g_W[id.x] = tf32r(v.x);
        g_W[id.y] = tf32r(v.y);
        g_W[id.z] = tf32r(v.z);
        g_W[id.w] = tf32r(v.w);
    }
}

// ---------------- stage load: gmem -> SW128-swizzled smem via cp.async ----------------
__device__ __forceinline__ void load_stage(uint32_t sb, int mbase, int nbase, int stage, int tid) {
    int slot = stage & (STAGES - 1);
    int k0 = stage * BK;
    uint32_t abase = sb + slot * STAGE_BYTES;
    uint32_t bbase = abase + A_BYTES;
    // A tile: 128 rows x 32 floats = 1024 16B-chunks (8 per row); 4 per thread
    #pragma unroll
    for (int i = 0; i < 4; i++) {
        int q = tid + i * 256;
        int row = q >> 3, c = q & 7;
        const float* g = g_xr + (mbase + row) * NIN + k0 + c * 4;
        uint32_t off = row * 128 + c * 16;
        cpasync16(abase + (off ^ ((off >> 3) & 0x70)), g);
    }
    // B tile: 64 rows x 32 floats = 512 chunks; 2 per thread
    #pragma unroll
    for (int i = 0; i < 2; i++) {
        int q = tid + i * 256;
        int row = q >> 3, c = q & 7;
        const float* g = g_W + (nbase + row) * NIN + k0 + c * 4;
        uint32_t off = row * 128 + c * 16;
        cpasync16(bbase + (off ^ ((off >> 3) & 0x70)), g);
    }
}

// ---------------- GEMM: out[256,4096] = xr @ W^T (tf32 mma.sync) ----------------
__global__ void __launch_bounds__(256, 1) gemm_kernel(float* __restrict__ out) {
    extern __shared__ char smem[];
    uint32_t sb = s2u(smem);
    int tid = threadIdx.x;
    int lane = tid & 31;
    int wid = tid >> 5;            // 8 warps: 4 (M) x 2 (N)
    int wm = wid >> 1;             // 0..3  -> warp M offset wm*32
    int wn = wid & 1;              // 0..1  -> warp N offset wn*32
    int mbase = blockIdx.y * BM;
    int nbase = blockIdx.x * BN;

    int lr = lane & 7;             // row-within-matrix for ldmatrix
    int lq = lane >> 3;            // matrix index 0..3

    // ldmatrix address components (swizzle XOR depends only on row&7)
    // A: mat layout -> row = wm*32 + mt*16 + (lq&1)*8 + lr ; 16B-chunk = ks*2 + (lq>>1)
    uint32_t arow[2], axor[2];
    #pragma unroll
    for (int mt = 0; mt < 2; mt++) {
        uint32_t r = wm * 32 + mt * 16 + (lq & 1) * 8 + lr;
        arow[mt] = r * 128;
        axor[mt] = (r & 7) << 4;
    }
    uint32_t acol = (lq >> 1) * 16;
    // B: row = wn*32 + p*16 + (lq>>1)*8 + lr ; chunk = ks*2 + (lq&1)
    uint32_t brow[2], bxor[2];
    #pragma unroll
    for (int p = 0; p < 2; p++) {
        uint32_t r = wn * 32 + p * 16 + (lq >> 1) * 8 + lr;
        brow[p] = r * 128;
        bxor[p] = (r & 7) << 4;
    }
    uint32_t bcol = (lq & 1) * 16;

    float acc[2][4][4];
    #pragma unroll
    for (int mt = 0; mt < 2; mt++)
        #pragma unroll
        for (int nt = 0; nt < 4; nt++)
            #pragma unroll
            for (int j = 0; j < 4; j++) acc[mt][nt][j] = 0.0f;

    // prologue: prefetch STAGES-1 stages
    #pragma unroll
    for (int l = 0; l < STAGES - 1; l++) {
        load_stage(sb, mbase, nbase, l, tid);
        CP_COMMIT();
    }

    for (int s = 0; s < NS; s++) {
        int slot = s & (STAGES - 1);
        CP_WAIT();
        __syncthreads();

        if (s + STAGES - 1 < NS) load_stage(sb, mbase, nbase, s + STAGES - 1, tid);
        CP_COMMIT();

        uint32_t aBase = sb + slot * STAGE_BYTES;
        uint32_t bBase = aBase + A_BYTES;

        #pragma unroll
        for (int ks = 0; ks < 4; ks++) {
            uint32_t a[2][4], b[2][4];
            #pragma unroll
            for (int mt = 0; mt < 2; mt++)
                ldsm4(a[mt][0], a[mt][1], a[mt][2], a[mt][3],
                      aBase + arow[mt] + ((ks * 32 + acol) ^ axor[mt]));
            #pragma unroll
            for (int p = 0; p < 2; p++)
                ldsm4(b[p][0], b[p][1], b[p][2], b[p][3],
                      bBase + brow[p] + ((ks * 32 + bcol) ^ bxor[p]));
            #pragma unroll
            for (int mt = 0; mt < 2; mt++) {
                #pragma unroll
                for (int nt = 0; nt < 4; nt++) {
                    const uint32_t* bp = b[nt >> 1];
                    mma8(acc[mt][nt], a[mt], bp[(nt & 1) * 2], bp[(nt & 1) * 2 + 1]);
                }
            }
        }
    }

    // epilogue: write accumulators (fp32) straight to gmem
    int g = lane >> 2, tg = lane & 3;
    #pragma unroll
    for (int mt = 0; mt < 2; mt++) {
        #pragma unroll
        for (int nt = 0; nt < 4; nt++) {
            int row = mbase + wm * 32 + mt * 16 + g;
            int col = nbase + wn * 32 + nt * 8 + tg * 2;
            float2* p0 = reinterpret_cast<float2*>(out + (size_t)row * NOUT + col);
            float2* p1 = reinterpret_cast<float2*>(out + (size_t)(row + 8) * NOUT + col);
            *p0 = make_float2(acc[mt][nt][0], acc[mt][nt][1]);
            *p1 = make_float2(acc[mt][nt][2], acc[mt][nt][3]);
        }
    }
}

// ---------------- launch ----------------
extern "C" void kernel_launch(void* const* d_in, const int* in_sizes, int n_in,
                              void* d_out, int out_size) {
    const float* x    = (const float*)d_in[0];
    const float* vals = (const float*)d_in[1];
    const int*   idx  = (const int*)d_in[2];
    float* out = (float*)d_out;
    (void)in_sizes; (void)n_in; (void)out_size;

    cudaFuncSetAttribute(gemm_kernel, cudaFuncAttributeMaxDynamicSharedMemorySize, SMEM_TOTAL);

    int xq = TOKENS * NIN / 4;
    round_x_kernel<<<(xq + 255) / 256, 256>>>((const float4*)x, xq);

    int sq = NSPARSE / 4;
    scatter_kernel<<<(sq + 255) / 256, 256>>>((const float4*)vals, (const int4*)idx, sq);

    dim3 grid(NOUT / BN, TOKENS / BM);    // (64, 2) = 128 CTAs
    gemm_kernel<<<grid, 256, SMEM_TOTAL>>>(out);
}

// round 3
// speedup vs baseline: 1.5669x; 1.5669x over previous
#include <cuda_runtime.h>
#include <cuda_fp16.h>
#include <cstdint>

#define TOKENS 256
#define NOUT 4096
#define NIN 4096
#define NSPARSE 8388608

// ---------------- GEMM tiling (fp16 mma.sync m16n8k16; sm_100 non-'a' safe) ----------------
#define BM 128
#define BN 64
#define BK 64                         // halfs per K-stage = 128 bytes (one swizzle row)
#define STAGES 4
#define NS (NIN / BK)                 // 64 K-stages

#define A_BYTES (BM * 128)            // 16 KB
#define B_BYTES (BN * 128)            // 8 KB
#define STAGE_BYTES (A_BYTES + B_BYTES)
#define SMEM_TOTAL (STAGES * STAGE_BYTES)   // 96 KB

// ---------------- persistent device scratch (zero-init at module load) ----------------
__device__ __half g_W[NOUT * NIN];     // 32 MB dense fp16 weight; untouched entries stay 0
__device__ __half g_xh[TOKENS * NIN];  // 2 MB fp16 activations

// ---------------- helpers ----------------
__device__ __forceinline__ uint32_t s2u(const void* p) {
    uint32_t a;
    asm("{ .reg .u64 t; cvta.to.shared.u64 t, %1; cvt.u32.u64 %0, t; }" : "=r"(a) : "l"(p));
    return a;
}

__device__ __forceinline__ void cpasync16(uint32_t saddr, const void* g) {
    asm volatile("cp.async.cg.shared.global [%0], [%1], 16;" :: "r"(saddr), "l"(g) : "memory");
}
#define CP_COMMIT() asm volatile("cp.async.commit_group;" ::: "memory")
#define CP_WAIT()   asm volatile("cp.async.wait_group %0;" :: "n"(STAGES - 2) : "memory")

__device__ __forceinline__ void ldsm4(uint32_t& r0, uint32_t& r1, uint32_t& r2, uint32_t& r3,
                                      uint32_t addr) {
    asm volatile("ldmatrix.sync.aligned.m8n8.x4.shared.b16 {%0,%1,%2,%3}, [%4];"
                 : "=r"(r0), "=r"(r1), "=r"(r2), "=r"(r3) : "r"(addr));
}

__device__ __forceinline__ void mma16(float* d, const uint32_t* a, uint32_t b0, uint32_t b1) {
    asm volatile(
        "mma.sync.aligned.m16n8k16.row.col.f32.f16.f16.f32 "
        "{%0,%1,%2,%3}, {%4,%5,%6,%7}, {%8,%9}, {%0,%1,%2,%3};"
        : "+f"(d[0]), "+f"(d[1]), "+f"(d[2]), "+f"(d[3])
        : "r"(a[0]), "r"(a[1]), "r"(a[2]), "r"(a[3]), "r"(b0), "r"(b1));
}

// ---------------- prep kernels ----------------
__global__ void round_x_kernel(const float4* __restrict__ x, int nq) {
    int i = blockIdx.x * blockDim.x + threadIdx.x;
    if (i < nq) {
        float4 v = x[i];
        __half2* o = reinterpret_cast<__half2*>(g_xh);
        o[2 * i]     = __float22half2_rn(make_float2(v.x, v.y));
        o[2 * i + 1] = __float22half2_rn(make_float2(v.z, v.w));
    }
}

__global__ void scatter_kernel(const float4* __restrict__ vals, const int4* __restrict__ idx,
                               int nq) {
    int i = blockIdx.x * blockDim.x + threadIdx.x;
    if (i < nq) {
        float4 v = vals[i];
        int4 id = idx[i];
        // RN conversion to fp16 (same 10 mantissa bits as tf32) -> zero-mean error
        g_W[id.x] = __float2half_rn(v.x);
        g_W[id.y] = __float2half_rn(v.y);
        g_W[id.z] = __float2half_rn(v.z);
        g_W[id.w] = __float2half_rn(v.w);
    }
}

// ---------------- stage load: gmem -> swizzled smem via cp.async ----------------
// Each smem row = 128 bytes = 64 halfs; swizzle: off ^= ((off>>3)&0x70)
__device__ __forceinline__ void load_stage(uint32_t sb, int mbase, int nbase, int stage, int tid) {
    int slot = stage & (STAGES - 1);
    int k0 = stage * BK;
    uint32_t abase = sb + slot * STAGE_BYTES;
    uint32_t bbase = abase + A_BYTES;
    // A tile: 128 rows x 128B = 1024 16B-chunks (8 per row); 4 per thread
    #pragma unroll
    for (int i = 0; i < 4; i++) {
        int q = tid + i * 256;
        int row = q >> 3, c = q & 7;
        const __half* g = g_xh + (mbase + row) * NIN + k0 + c * 8;
        uint32_t off = row * 128 + c * 16;
        cpasync16(abase + (off ^ ((off >> 3) & 0x70)), g);
    }
    // B tile: 64 rows x 128B = 512 chunks; 2 per thread
    #pragma unroll
    for (int i = 0; i < 2; i++) {
        int q = tid + i * 256;
        int row = q >> 3, c = q & 7;
        const __half* g = g_W + (size_t)(nbase + row) * NIN + k0 + c * 8;
        uint32_t off = row * 128 + c * 16;
        cpasync16(bbase + (off ^ ((off >> 3) & 0x70)), g);
    }
}

// ---------------- GEMM: out[256,4096] = xh @ W^T (fp16 mma, fp32 accum) ----------------
__global__ void __launch_bounds__(256, 1) gemm_kernel(float* __restrict__ out) {
    extern __shared__ char smem[];
    uint32_t sb = s2u(smem);
    int tid = threadIdx.x;
    int lane = tid & 31;
    int wid = tid >> 5;            // 8 warps: 4 (M) x 2 (N)
    int wm = wid >> 1;             // warp M offset wm*32
    int wn = wid & 1;              // warp N offset wn*32
    int mbase = blockIdx.y * BM;
    int nbase = blockIdx.x * BN;

    int lr = lane & 7;
    int lq = lane >> 3;            // ldmatrix sub-matrix index 0..3

    // A (m16k16 row-major): row = wm*32 + mt*16 + (lq&1)*8 + lr ; colByte = ks*32 + (lq>>1)*16
    uint32_t arow[2], axor[2];
    #pragma unroll
    for (int mt = 0; mt < 2; mt++) {
        uint32_t r = wm * 32 + mt * 16 + (lq & 1) * 8 + lr;
        arow[mt] = r * 128;
        axor[mt] = (r & 7) << 4;
    }
    uint32_t acol = (lq >> 1) * 16;
    // B (n16k16 per x4 load): row(n) = wn*32 + p*16 + (lq>>1)*8 + lr ; colByte = ks*32 + (lq&1)*16
    uint32_t brow[2], bxor[2];
    #pragma unroll
    for (int p = 0; p < 2; p++) {
        uint32_t r = wn * 32 + p * 16 + (lq >> 1) * 8 + lr;
        brow[p] = r * 128;
        bxor[p] = (r & 7) << 4;
    }
    uint32_t bcol = (lq & 1) * 16;

    float acc[2][4][4];
    #pragma unroll
    for (int mt = 0; mt < 2; mt++)
        #pragma unroll
        for (int nt = 0; nt < 4; nt++)
            #pragma unroll
            for (int j = 0; j < 4; j++) acc[mt][nt][j] = 0.0f;

    #pragma unroll
    for (int l = 0; l < STAGES - 1; l++) {
        load_stage(sb, mbase, nbase, l, tid);
        CP_COMMIT();
    }

    for (int s = 0; s < NS; s++) {
        int slot = s & (STAGES - 1);
        CP_WAIT();
        __syncthreads();

        if (s + STAGES - 1 < NS) load_stage(sb, mbase, nbase, s + STAGES - 1, tid);
        CP_COMMIT();

        uint32_t aBase = sb + slot * STAGE_BYTES;
        uint32_t bBase = aBase + A_BYTES;

        #pragma unroll
        for (int ks = 0; ks < 4; ks++) {     // 4 x k16 per 128B stage row
            uint32_t a[2][4], b[2][4];
            #pragma unroll
            for (int mt = 0; mt < 2; mt++)
                ldsm4(a[mt][0], a[mt][1], a[mt][2], a[mt][3],
                      aBase + arow[mt] + ((ks * 32 + acol) ^ axor[mt]));
            #pragma unroll
            for (int p = 0; p < 2; p++)
                ldsm4(b[p][0], b[p][1], b[p][2], b[p][3],
                      bBase + brow[p] + ((ks * 32 + bcol) ^ bxor[p]));
            #pragma unroll
            for (int mt = 0; mt < 2; mt++) {
                #pragma unroll
                for (int nt = 0; nt < 4; nt++) {
                    const uint32_t* bp = b[nt >> 1];
                    mma16(acc[mt][nt], a[mt], bp[(nt & 1) * 2], bp[(nt & 1) * 2 + 1]);
                }
            }
        }
    }

    // epilogue: fp32 accumulators straight to gmem
    int g = lane >> 2, tg = lane & 3;
    #pragma unroll
    for (int mt = 0; mt < 2; mt++) {
        #pragma unroll
        for (int nt = 0; nt < 4; nt++) {
            int row = mbase + wm * 32 + mt * 16 + g;
            int col = nbase + wn * 32 + nt * 8 + tg * 2;
            float2* p0 = reinterpret_cast<float2*>(out + (size_t)row * NOUT + col);
            float2* p1 = reinterpret_cast<float2*>(out + (size_t)(row + 8) * NOUT + col);
            *p0 = make_float2(acc[mt][nt][0], acc[mt][nt][1]);
            *p1 = make_float2(acc[mt][nt][2], acc[mt][nt][3]);
        }
    }
}

// ---------------- launch ----------------
extern "C" void kernel_launch(void* const* d_in, const int* in_sizes, int n_in,
                              void* d_out, int out_size) {
    const float* x    = (const float*)d_in[0];
    const float* vals = (const float*)d_in[1];
    const int*   idx  = (const int*)d_in[2];
    float* out = (float*)d_out;
    (void)in_sizes; (void)n_in; (void)out_size;

    cudaFuncSetAttribute(gemm_kernel, cudaFuncAttributeMaxDynamicSharedMemorySize, SMEM_TOTAL);

    int xq = TOKENS * NIN / 4;
    round_x_kernel<<<(xq + 255) / 256, 256>>>((const float4*)x, xq);

    int sq = NSPARSE / 4;
    scatter_kernel<<<(sq + 255) / 256, 256>>>((const float4*)vals, (const int4*)idx, sq);

    dim3 grid(NOUT / BN, TOKENS / BM);    // (64, 2) = 128 CTAs
    gemm_kernel<<<grid, 256, SMEM_TOTAL>>>(out);
}

// round 4
// speedup vs baseline: 1.5843x; 1.0111x over previous
#include <cuda_runtime.h>
#include <cuda_fp16.h>
#include <cstdint>

#define TOKENS 256
#define NOUT 4096
#define NIN 4096
#define NSPARSE 8388608

// ---------------- GEMM tiling (fp16 mma.sync m16n8k16; sm_100 non-'a' safe) ----------------
#define BM 128
#define BN 64
#define BK 64                         // halfs per K-stage = 128 bytes (one swizzle row)
#define STAGES 4
#define NS (NIN / BK)                 // 64 K-stages

#define A_BYTES (BM * 128)            // 16 KB
#define B_BYTES (BN * 128)            // 8 KB
#define STAGE_BYTES (A_BYTES + B_BYTES)
#define SMEM_TOTAL (STAGES * STAGE_BYTES)   // 96 KB

// prep fusion: first X_BLOCKS blocks convert x, remaining blocks scatter W
#define X_QUADS (TOKENS * NIN / 4)          // 262144 float4 elements
#define X_BLOCKS (X_QUADS / 256)            // 1024
#define S_QUADS (NSPARSE / 4)               // 2097152
#define S_BLOCKS (S_QUADS / 256)            // 8192

// ---------------- persistent device scratch (zero-init at module load) ----------------
__device__ __half g_W[NOUT * NIN];     // 32 MB dense fp16 weight; untouched entries stay 0
__device__ __half g_xh[TOKENS * NIN];  // 2 MB fp16 activations

// ---------------- helpers ----------------
__device__ __forceinline__ uint32_t s2u(const void* p) {
    uint32_t a;
    asm("{ .reg .u64 t; cvta.to.shared.u64 t, %1; cvt.u32.u64 %0, t; }" : "=r"(a) : "l"(p));
    return a;
}

__device__ __forceinline__ void cpasync16(uint32_t saddr, const void* g) {
    asm volatile("cp.async.cg.shared.global [%0], [%1], 16;" :: "r"(saddr), "l"(g) : "memory");
}
#define CP_COMMIT() asm volatile("cp.async.commit_group;" ::: "memory")
#define CP_WAIT()   asm volatile("cp.async.wait_group %0;" :: "n"(STAGES - 2) : "memory")

__device__ __forceinline__ void ldsm4(uint32_t& r0, uint32_t& r1, uint32_t& r2, uint32_t& r3,
                                      uint32_t addr) {
    asm volatile("ldmatrix.sync.aligned.m8n8.x4.shared.b16 {%0,%1,%2,%3}, [%4];"
                 : "=r"(r0), "=r"(r1), "=r"(r2), "=r"(r3) : "r"(addr));
}

__device__ __forceinline__ void mma16(float* d, const uint32_t* a, uint32_t b0, uint32_t b1) {
    asm volatile(
        "mma.sync.aligned.m16n8k16.row.col.f32.f16.f16.f32 "
        "{%0,%1,%2,%3}, {%4,%5,%6,%7}, {%8,%9}, {%0,%1,%2,%3};"
        : "+f"(d[0]), "+f"(d[1]), "+f"(d[2]), "+f"(d[3])
        : "r"(a[0]), "r"(a[1]), "r"(a[2]), "r"(a[3]), "r"(b0), "r"(b1));
}

// ---------------- fused prep: x fp32->fp16 convert + W scatter in ONE launch ----------------
__global__ void __launch_bounds__(256) prep_kernel(const float4* __restrict__ x,
                                                   const float4* __restrict__ vals,
                                                   const int4* __restrict__ idx) {
    int b = blockIdx.x;
    if (b < X_BLOCKS) {
        int i = b * 256 + threadIdx.x;
        float4 v = x[i];
        __half2* o = reinterpret_cast<__half2*>(g_xh);
        o[2 * i]     = __float22half2_rn(make_float2(v.x, v.y));
        o[2 * i + 1] = __float22half2_rn(make_float2(v.z, v.w));
    } else {
        int i = (b - X_BLOCKS) * 256 + threadIdx.x;
        float4 v = vals[i];
        int4 id = idx[i];
        // RN conversion to fp16 (10 mantissa bits, same as tf32) -> zero-mean error
        g_W[id.x] = __float2half_rn(v.x);
        g_W[id.y] = __float2half_rn(v.y);
        g_W[id.z] = __float2half_rn(v.z);
        g_W[id.w] = __float2half_rn(v.w);
    }
}

// ---------------- stage load: gmem -> swizzled smem via cp.async ----------------
// Each smem row = 128 bytes = 64 halfs; swizzle: off ^= ((off>>3)&0x70)
__device__ __forceinline__ void load_stage(uint32_t sb, int mbase, int nbase, int stage, int tid) {
    int slot = stage & (STAGES - 1);
    int k0 = stage * BK;
    uint32_t abase = sb + slot * STAGE_BYTES;
    uint32_t bbase = abase + A_BYTES;
    // A tile: 128 rows x 128B = 1024 16B-chunks (8 per row); 4 per thread
    #pragma unroll
    for (int i = 0; i < 4; i++) {
        int q = tid + i * 256;
        int row = q >> 3, c = q & 7;
        const __half* g = g_xh + (mbase + row) * NIN + k0 + c * 8;
        uint32_t off = row * 128 + c * 16;
        cpasync16(abase + (off ^ ((off >> 3) & 0x70)), g);
    }
    // B tile: 64 rows x 128B = 512 chunks; 2 per thread
    #pragma unroll
    for (int i = 0; i < 2; i++) {
        int q = tid + i * 256;
        int row = q >> 3, c = q & 7;
        const __half* g = g_W + (size_t)(nbase + row) * NIN + k0 + c * 8;
        uint32_t off = row * 128 + c * 16;
        cpasync16(bbase + (off ^ ((off >> 3) & 0x70)), g);
    }
}

// ---------------- GEMM: out[256,4096] = xh @ W^T (fp16 mma, fp32 accum) ----------------
__global__ void __launch_bounds__(256, 1) gemm_kernel(float* __restrict__ out) {
    extern __shared__ char smem[];
    uint32_t sb = s2u(smem);
    int tid = threadIdx.x;
    int lane = tid & 31;
    int wid = tid >> 5;            // 8 warps: 4 (M) x 2 (N)
    int wm = wid >> 1;             // warp M offset wm*32
    int wn = wid & 1;              // warp N offset wn*32
    int mbase = blockIdx.y * BM;
    int nbase = blockIdx.x * BN;

    int lr = lane & 7;
    int lq = lane >> 3;            // ldmatrix sub-matrix index 0..3

    // A (m16k16 row-major): row = wm*32 + mt*16 + (lq&1)*8 + lr ; colByte = ks*32 + (lq>>1)*16
    uint32_t arow[2], axor[2];
    #pragma unroll
    for (int mt = 0; mt < 2; mt++) {
        uint32_t r = wm * 32 + mt * 16 + (lq & 1) * 8 + lr;
        arow[mt] = r * 128;
        axor[mt] = (r & 7) << 4;
    }
    uint32_t acol = (lq >> 1) * 16;
    // B (n16k16 per x4 load): row(n) = wn*32 + p*16 + (lq>>1)*8 + lr ; colByte = ks*32 + (lq&1)*16
    uint32_t brow[2], bxor[2];
    #pragma unroll
    for (int p = 0; p < 2; p++) {
        uint32_t r = wn * 32 + p * 16 + (lq >> 1) * 8 + lr;
        brow[p] = r * 128;
        bxor[p] = (r & 7) << 4;
    }
    uint32_t bcol = (lq & 1) * 16;

    float acc[2][4][4];
    #pragma unroll
    for (int mt = 0; mt < 2; mt++)
        #pragma unroll
        for (int nt = 0; nt < 4; nt++)
            #pragma unroll
            for (int j = 0; j < 4; j++) acc[mt][nt][j] = 0.0f;

    #pragma unroll
    for (int l = 0; l < STAGES - 1; l++) {
        load_stage(sb, mbase, nbase, l, tid);
        CP_COMMIT();
    }

    for (int s = 0; s < NS; s++) {
        int slot = s & (STAGES - 1);
        CP_WAIT();
        __syncthreads();

        if (s + STAGES - 1 < NS) load_stage(sb, mbase, nbase, s + STAGES - 1, tid);
        CP_COMMIT();

        uint32_t aBase = sb + slot * STAGE_BYTES;
        uint32_t bBase = aBase + A_BYTES;

        #pragma unroll
        for (int ks = 0; ks < 4; ks++) {     // 4 x k16 per 128B stage row
            uint32_t a[2][4], b[2][4];
            #pragma unroll
            for (int mt = 0; mt < 2; mt++)
                ldsm4(a[mt][0], a[mt][1], a[mt][2], a[mt][3],
                      aBase + arow[mt] + ((ks * 32 + acol) ^ axor[mt]));
            #pragma unroll
            for (int p = 0; p < 2; p++)
                ldsm4(b[p][0], b[p][1], b[p][2], b[p][3],
                      bBase + brow[p] + ((ks * 32 + bcol) ^ bxor[p]));
            #pragma unroll
            for (int mt = 0; mt < 2; mt++) {
                #pragma unroll
                for (int nt = 0; nt < 4; nt++) {
                    const uint32_t* bp = b[nt >> 1];
                    mma16(acc[mt][nt], a[mt], bp[(nt & 1) * 2], bp[(nt & 1) * 2 + 1]);
                }
            }
        }
    }

    // epilogue: fp32 accumulators straight to gmem
    int g = lane >> 2, tg = lane & 3;
    #pragma unroll
    for (int mt = 0; mt < 2; mt++) {
        #pragma unroll
        for (int nt = 0; nt < 4; nt++) {
            int row = mbase + wm * 32 + mt * 16 + g;
            int col = nbase + wn * 32 + nt * 8 + tg * 2;
            float2* p0 = reinterpret_cast<float2*>(out + (size_t)row * NOUT + col);
            float2* p1 = reinterpret_cast<float2*>(out + (size_t)(row + 8) * NOUT + col);
            *p0 = make_float2(acc[mt][nt][0], acc[mt][nt][1]);
            *p1 = make_float2(acc[mt][nt][2], acc[mt][nt][3]);
        }
    }
}

// ---------------- launch ----------------
extern "C" void kernel_launch(void* const* d_in, const int* in_sizes, int n_in,
                              void* d_out, int out_size) {
    const float* x    = (const float*)d_in[0];
    const float* vals = (const float*)d_in[1];
    const int*   idx  = (const int*)d_in[2];
    float* out = (float*)d_out;
    (void)in_sizes; (void)n_in; (void)out_size;

    cudaFuncSetAttribute(gemm_kernel, cudaFuncAttributeMaxDynamicSharedMemorySize, SMEM_TOTAL);

    prep_kernel<<<X_BLOCKS + S_BLOCKS, 256>>>((const float4*)x, (const float4*)vals,
                                              (const int4*)idx);

    dim3 grid(NOUT / BN, TOKENS / BM);    // (64, 2) = 128 CTAs
    gemm_kernel<<<grid, 256, SMEM_TOTAL>>>(out);
}

// round 5
// speedup vs baseline: 1.7016x; 1.0741x over previous
#include <cuda_runtime.h>
#include <cuda_fp16.h>
#include <cstdint>

#define TOKENS 256
#define NOUT 4096
#define NIN 4096
#define NSPARSE 8388608

// ---------------- GEMM tiling (fp16 mma.sync m16n8k16; sm_100 non-'a' safe) ----------------
#define BM 64
#define BN 64
#define BK 64                         // halfs per K-stage = 128 bytes (one swizzle row)
#define STAGES 4
#define NS (NIN / BK)                 // 64 K-stages
#define NTHREADS 128                  // 4 warps: 2 (M) x 2 (N), warp tile 32x32

#define A_BYTES (BM * 128)            // 8 KB
#define B_BYTES (BN * 128)            // 8 KB
#define STAGE_BYTES (A_BYTES + B_BYTES)
#define SMEM_TOTAL (STAGES * STAGE_BYTES)   // 64 KB -> 2 CTAs/SM

// prep fusion: first X_BLOCKS blocks convert x, remaining blocks scatter W
#define X_QUADS (TOKENS * NIN / 4)          // 262144
#define X_BLOCKS (X_QUADS / 256)            // 1024
#define S_QUADS (NSPARSE / 4)               // 2097152
#define S_BLOCKS (S_QUADS / 256)            // 8192

// ---------------- persistent device scratch (zero-init at module load) ----------------
__device__ __half g_W[NOUT * NIN];     // 32 MB dense fp16 weight; untouched entries stay 0
__device__ __half g_xh[TOKENS * NIN];  // 2 MB fp16 activations

// ---------------- helpers ----------------
__device__ __forceinline__ uint32_t s2u(const void* p) {
    uint32_t a;
    asm("{ .reg .u64 t; cvta.to.shared.u64 t, %1; cvt.u32.u64 %0, t; }" : "=r"(a) : "l"(p));
    return a;
}

__device__ __forceinline__ void cpasync16(uint32_t saddr, const void* g) {
    asm volatile("cp.async.cg.shared.global [%0], [%1], 16;" :: "r"(saddr), "l"(g) : "memory");
}
#define CP_COMMIT() asm volatile("cp.async.commit_group;" ::: "memory")
#define CP_WAIT()   asm volatile("cp.async.wait_group %0;" :: "n"(STAGES - 2) : "memory")

__device__ __forceinline__ void ldsm4(uint32_t& r0, uint32_t& r1, uint32_t& r2, uint32_t& r3,
                                      uint32_t addr) {
    asm volatile("ldmatrix.sync.aligned.m8n8.x4.shared.b16 {%0,%1,%2,%3}, [%4];"
                 : "=r"(r0), "=r"(r1), "=r"(r2), "=r"(r3) : "r"(addr));
}

__device__ __forceinline__ void mma16(float* d, const uint32_t* a, uint32_t b0, uint32_t b1) {
    asm volatile(
        "mma.sync.aligned.m16n8k16.row.col.f32.f16.f16.f32 "
        "{%0,%1,%2,%3}, {%4,%5,%6,%7}, {%8,%9}, {%0,%1,%2,%3};"
        : "+f"(d[0]), "+f"(d[1]), "+f"(d[2]), "+f"(d[3])
        : "r"(a[0]), "r"(a[1]), "r"(a[2]), "r"(a[3]), "r"(b0), "r"(b1));
}

// ---------------- fused prep: x fp32->fp16 convert + W scatter in ONE launch ----------------
__global__ void __launch_bounds__(256) prep_kernel(const float4* __restrict__ x,
                                                   const float4* __restrict__ vals,
                                                   const int4* __restrict__ idx) {
    int b = blockIdx.x;
    if (b < X_BLOCKS) {
        int i = b * 256 + threadIdx.x;
        float4 v = x[i];
        __half2* o = reinterpret_cast<__half2*>(g_xh);
        o[2 * i]     = __float22half2_rn(make_float2(v.x, v.y));
        o[2 * i + 1] = __float22half2_rn(make_float2(v.z, v.w));
    } else {
        int i = (b - X_BLOCKS) * 256 + threadIdx.x;
        float4 v = vals[i];
        int4 id = idx[i];
        // RN conversion to fp16 (10 mantissa bits, same as tf32) -> zero-mean error
        g_W[id.x] = __float2half_rn(v.x);
        g_W[id.y] = __float2half_rn(v.y);
        g_W[id.z] = __float2half_rn(v.z);
        g_W[id.w] = __float2half_rn(v.w);
    }
}

// ---------------- stage load: gmem -> swizzled smem via cp.async ----------------
// Each smem row = 128 bytes = 64 halfs; swizzle: off ^= ((off>>3)&0x70)
__device__ __forceinline__ void load_stage(uint32_t sb, int mbase, int nbase, int stage, int tid) {
    int slot = stage & (STAGES - 1);
    int k0 = stage * BK;
    uint32_t abase = sb + slot * STAGE_BYTES;
    uint32_t bbase = abase + A_BYTES;
    // A tile: 64 rows x 8 16B-chunks = 512 chunks over 128 threads -> 4 each
    #pragma unroll
    for (int i = 0; i < 4; i++) {
        int q = tid + i * NTHREADS;
        int row = q >> 3, c = q & 7;
        const __half* g = g_xh + (mbase + row) * NIN + k0 + c * 8;
        uint32_t off = row * 128 + c * 16;
        cpasync16(abase + (off ^ ((off >> 3) & 0x70)), g);
    }
    // B tile: 64 rows x 8 chunks = 512 chunks -> 4 each
    #pragma unroll
    for (int i = 0; i < 4; i++) {
        int q = tid + i * NTHREADS;
        int row = q >> 3, c = q & 7;
        const __half* g = g_W + (size_t)(nbase + row) * NIN + k0 + c * 8;
        uint32_t off = row * 128 + c * 16;
        cpasync16(bbase + (off ^ ((off >> 3) & 0x70)), g);
    }
}

// ---------------- GEMM: out[256,4096] = xh @ W^T (fp16 mma, fp32 accum) ----------------
__global__ void __launch_bounds__(NTHREADS, 2) gemm_kernel(float* __restrict__ out) {
    extern __shared__ char smem[];
    uint32_t sb = s2u(smem);
    int tid = threadIdx.x;
    int lane = tid & 31;
    int wid = tid >> 5;            // 4 warps: 2 (M) x 2 (N)
    int wm = wid >> 1;             // warp M offset wm*32
    int wn = wid & 1;              // warp N offset wn*32
    int mbase = blockIdx.y * BM;
    int nbase = blockIdx.x * BN;

    int lr = lane & 7;
    int lq = lane >> 3;            // ldmatrix sub-matrix index 0..3

    // A (m16k16 row-major): row = wm*32 + mt*16 + (lq&1)*8 + lr ; colByte = ks*32 + (lq>>1)*16
    uint32_t arow[2], axor[2];
    #pragma unroll
    for (int mt = 0; mt < 2; mt++) {
        uint32_t r = wm * 32 + mt * 16 + (lq & 1) * 8 + lr;
        arow[mt] = r * 128;
        axor[mt] = (r & 7) << 4;
    }
    uint32_t acol = (lq >> 1) * 16;
    // B (n16k16 per x4 load): row(n) = wn*32 + p*16 + (lq>>1)*8 + lr ; colByte = ks*32 + (lq&1)*16
    uint32_t brow[2], bxor[2];
    #pragma unroll
    for (int p = 0; p < 2; p++) {
        uint32_t r = wn * 32 + p * 16 + (lq >> 1) * 8 + lr;
        brow[p] = r * 128;
        bxor[p] = (r & 7) << 4;
    }
    uint32_t bcol = (lq & 1) * 16;

    float acc[2][4][4];
    #pragma unroll
    for (int mt = 0; mt < 2; mt++)
        #pragma unroll
        for (int nt = 0; nt < 4; nt++)
            #pragma unroll
            for (int j = 0; j < 4; j++) acc[mt][nt][j] = 0.0f;

    #pragma unroll
    for (int l = 0; l < STAGES - 1; l++) {
        load_stage(sb, mbase, nbase, l, tid);
        CP_COMMIT();
    }

    for (int s = 0; s < NS; s++) {
        int slot = s & (STAGES - 1);
        CP_WAIT();
        __syncthreads();

        if (s + STAGES - 1 < NS) load_stage(sb, mbase, nbase, s + STAGES - 1, tid);
        CP_COMMIT();

        uint32_t aBase = sb + slot * STAGE_BYTES;
        uint32_t bBase = aBase + A_BYTES;

        #pragma unroll
        for (int ks = 0; ks < 4; ks++) {     // 4 x k16 per 128B stage row
            uint32_t a[2][4], b[2][4];
            #pragma unroll
            for (int mt = 0; mt < 2; mt++)
                ldsm4(a[mt][0], a[mt][1], a[mt][2], a[mt][3],
                      aBase + arow[mt] + ((ks * 32 + acol) ^ axor[mt]));
            #pragma unroll
            for (int p = 0; p < 2; p++)
                ldsm4(b[p][0], b[p][1], b[p][2], b[p][3],
                      bBase + brow[p] + ((ks * 32 + bcol) ^ bxor[p]));
            #pragma unroll
            for (int mt = 0; mt < 2; mt++) {
                #pragma unroll
                for (int nt = 0; nt < 4; nt++) {
                    const uint32_t* bp = b[nt >> 1];
                    mma16(acc[mt][nt], a[mt], bp[(nt & 1) * 2], bp[(nt & 1) * 2 + 1]);
                }
            }
        }
    }

    // epilogue: fp32 accumulators straight to gmem
    int g = lane >> 2, tg = lane & 3;
    #pragma unroll
    for (int mt = 0; mt < 2; mt++) {
        #pragma unroll
        for (int nt = 0; nt < 4; nt++) {
            int row = mbase + wm * 32 + mt * 16 + g;
            int col = nbase + wn * 32 + nt * 8 + tg * 2;
            float2* p0 = reinterpret_cast<float2*>(out + (size_t)row * NOUT + col);
            float2* p1 = reinterpret_cast<float2*>(out + (size_t)(row + 8) * NOUT + col);
            *p0 = make_float2(acc[mt][nt][0], acc[mt][nt][1]);
            *p1 = make_float2(acc[mt][nt][2], acc[mt][nt][3]);
        }
    }
}

// ---------------- launch ----------------
extern "C" void kernel_launch(void* const* d_in, const int* in_sizes, int n_in,
                              void* d_out, int out_size) {
    const float* x    = (const float*)d_in[0];
    const float* vals = (const float*)d_in[1];
    const int*   idx  = (const int*)d_in[2];
    float* out = (float*)d_out;
    (void)in_sizes; (void)n_in; (void)out_size;

    cudaFuncSetAttribute(gemm_kernel, cudaFuncAttributeMaxDynamicSharedMemorySize, SMEM_TOTAL);

    prep_kernel<<<X_BLOCKS + S_BLOCKS, 256>>>((const float4*)x, (const float4*)vals,
                                              (const int4*)idx);

    dim3 grid(NOUT / BN, TOKENS / BM);    // (64, 4) = 256 CTAs, 2 resident per SM
    gemm_kernel<<<grid, NTHREADS, SMEM_TOTAL>>>(out);
}